// round 5
// baseline (speedup 1.0000x reference)
#include <cuda_runtime.h>
#include <cstdint>

#define T_STEPS 128
#define CIN 16
#define H 64
#define W 64
#define CO 64
#define PLANE (H*W)            // 4096
#define FRAME (CO*PLANE)       // 262144
#define TOTAL (T_STEPS*FRAME)  // 33554432

// conv scratch (static __device__ array: allocation-free per harness rules)
__device__ float g_conv[TOTAL];

#define TILE_H 8
#define TILE_W 16
#define XS_H   (TILE_H + 2)    // 10
#define XS_WD  (TILE_W + 2)    // 18 values per row
#define DS2    19              // row stride in u64 units (18 pairs + 1 pad)
#define CO_PER_BLK 16

// ---- packed f32x2 helpers (sm_103a FFMA2 path; only reachable via PTX) ----
__device__ __forceinline__ uint64_t pk2(float lo, float hi) {
    uint64_t r;
    asm("mov.b64 %0, {%1, %2};" : "=l"(r) : "f"(lo), "f"(hi));
    return r;
}
__device__ __forceinline__ void upk2(uint64_t v, float& lo, float& hi) {
    asm("mov.b64 {%0, %1}, %2;" : "=f"(lo), "=f"(hi) : "l"(v));
}
__device__ __forceinline__ uint64_t fma2(uint64_t a, uint64_t b, uint64_t c) {
    uint64_t r;
    asm("fma.rn.f32x2 %0, %1, %2, %3;" : "=l"(r) : "l"(a), "l"(b), "l"(c));
    return r;
}

// ---------------------------------------------------------------------------
// Conv kernel: grid (32 spatial tiles, 4 co-groups, 128 t), 128 threads.
// Thread computes 4 c_out x 4 w at one h; c_out packed in PAIRS (f32x2 acc).
// x halo tile stored PRE-DUPLICATED in smem: element i holds (v,v) as u64,
// so the (x,x) multiplicand is one aligned LDS.64 — no pack MOVs.
// Weight pairs (c,c+1) contiguous in ws (co-fastest) -> warp-uniform LDS.64.
// ---------------------------------------------------------------------------
__global__ __launch_bounds__(128, 6)
void conv_kernel(const float* __restrict__ x, const float* __restrict__ Wt,
                 const float* __restrict__ b) {
    __shared__ uint64_t xs2[CIN * XS_H * DS2];     // 3040 u64 = 24.3 KB
    __shared__ float    ws[CIN * 9 * CO_PER_BLK];  // 2304 f   =  9.2 KB

    const int tid  = threadIdx.x;
    const int t    = blockIdx.z;
    const int cog  = blockIdx.y;                   // co group (16 each)
    const int tile = blockIdx.x;                   // 0..31
    const int h0   = (tile >> 2) * TILE_H;
    const int w0   = (tile & 3) * TILE_W;
    const int co0  = cog * CO_PER_BLK;

    // Load weights: ws[(cin*9 + k)*16 + co_local]  (co fastest)
    #pragma unroll 4
    for (int i = tid; i < CIN * 9 * CO_PER_BLK; i += 128) {
        int col = i & 15;          // co local
        int k9  = i >> 4;          // cin*9 + kh*3 + kw
        ws[i] = Wt[(co0 + col) * (CIN * 9) + k9];
    }

    // Load x halo tile with zero padding, duplicated (v,v) per element
    const float* xt = x + (size_t)t * (CIN * PLANE);
    #pragma unroll 4
    for (int i = tid; i < CIN * XS_H * XS_WD; i += 128) {
        int c   = i % XS_WD;
        int rc  = i / XS_WD;
        int r   = rc % XS_H;
        int cin = rc / XS_H;
        int y   = h0 - 1 + r;
        int xg  = w0 - 1 + c;
        float v = 0.0f;
        if ((unsigned)y < (unsigned)H && (unsigned)xg < (unsigned)W)
            v = xt[cin * PLANE + y * W + xg];
        xs2[cin * (XS_H * DS2) + r * DS2 + c] = pk2(v, v);
    }
    __syncthreads();

    const int co_sub = tid >> 5;            // 0..3  (uniform within warp)
    const int lane   = tid & 31;
    const int hl     = lane >> 2;           // 0..7
    const int wl     = (lane & 3) * 4;      // 0,4,8,12
    const int co_b   = co_sub * 4;          // local co base

    // acc[p][w] packs c_out pair (co_b+2p, co_b+2p+1) at output column w
    uint64_t acc[2][4];
    #pragma unroll
    for (int p = 0; p < 2; p++) {
        float b0 = b[co0 + co_b + 2 * p];
        float b1 = b[co0 + co_b + 2 * p + 1];
        uint64_t bp = pk2(b0, b1);
        #pragma unroll
        for (int w = 0; w < 4; w++) acc[p][w] = bp;
    }

    #pragma unroll
    for (int cin = 0; cin < CIN; cin++) {
        #pragma unroll
        for (int kh = 0; kh < 3; kh++) {
            const uint64_t* row =
                &xs2[cin * (XS_H * DS2) + (hl + kh) * DS2 + wl];
            uint64_t xx[6];
            #pragma unroll
            for (int j = 0; j < 6; j++) xx[j] = row[j];   // LDS.64, no packs
            const float* wp = &ws[(cin * 9 + kh * 3) * CO_PER_BLK + co_b];
            #pragma unroll
            for (int p = 0; p < 2; p++) {
                // contiguous c-pairs -> aligned 8B warp-uniform broadcasts
                uint64_t wk0 = *(const uint64_t*)(wp + 2 * p);
                uint64_t wk1 = *(const uint64_t*)(wp + CO_PER_BLK + 2 * p);
                uint64_t wk2 = *(const uint64_t*)(wp + 2 * CO_PER_BLK + 2 * p);
                #pragma unroll
                for (int w = 0; w < 4; w++) {
                    acc[p][w] = fma2(xx[w],     wk0, acc[p][w]);
                    acc[p][w] = fma2(xx[w + 1], wk1, acc[p][w]);
                    acc[p][w] = fma2(xx[w + 2], wk2, acc[p][w]);
                }
            }
        }
    }

    // Unpack and store: one float4 per c_out (w-contiguous, 16B aligned)
    #pragma unroll
    for (int p = 0; p < 2; p++) {
        float lo[4], hi[4];
        #pragma unroll
        for (int w = 0; w < 4; w++) upk2(acc[p][w], lo[w], hi[w]);
        int co_e = co0 + co_b + 2 * p;
        size_t base = (size_t)t * FRAME + (h0 + hl) * W + (w0 + wl);
        *(float4*)&g_conv[base + (size_t)co_e * PLANE] =
            make_float4(lo[0], lo[1], lo[2], lo[3]);
        *(float4*)&g_conv[base + (size_t)(co_e + 1) * PLANE] =
            make_float4(hi[0], hi[1], hi[2], hi[3]);
    }
}

// ---------------------------------------------------------------------------
// Scan kernel: one thread per (c_out,h,w); sequential LIF over T.
// Already near HBM roofline (70% DRAM) — unchanged.
// ---------------------------------------------------------------------------
__global__ __launch_bounds__(256)
void scan_kernel(float* __restrict__ out) {
    const int idx = blockIdx.x * 256 + threadIdx.x;   // < FRAME
    const float* cp = g_conv + idx;
    float* op = out + idx;
    float state = 0.0f;
    #pragma unroll 8
    for (int t = 0; t < T_STEPS; t++) {
        float v = cp[(size_t)t * FRAME];
        state += v;
        float spike = (state >= 8.0f) ? 1.0f : 0.0f;      // fire
        state = (state >= 8.0f) ? 0.0f : state;           // reset-to-value 0
        state = (state > -1.0f) ? state : -1.0f;          // Threshold(-1,-1)
        op[(size_t)t * FRAME] = spike;
    }
}

extern "C" void kernel_launch(void* const* d_in, const int* in_sizes, int n_in,
                              void* d_out, int out_size) {
    // Identify inputs by unique element counts (robust to ordering)
    const float* x  = nullptr;
    const float* Wt = nullptr;
    const float* b  = nullptr;
    for (int i = 0; i < n_in; i++) {
        if (in_sizes[i] == T_STEPS * CIN * PLANE) x  = (const float*)d_in[i];
        else if (in_sizes[i] == CO * CIN * 9)     Wt = (const float*)d_in[i];
        else if (in_sizes[i] == CO)               b  = (const float*)d_in[i];
    }
    float* out = (float*)d_out;

    dim3 grid(32, 4, T_STEPS);      // 16384 blocks
    conv_kernel<<<grid, 128>>>(x, Wt, b);
    scan_kernel<<<FRAME / 256, 256>>>(out);
}

// round 6
// speedup vs baseline: 1.1869x; 1.1869x over previous
#include <cuda_runtime.h>
#include <cstdint>

#define T_STEPS 128
#define CIN 16
#define H 64
#define W 64
#define CO 64
#define PLANE (H*W)            // 4096
#define FRAME (CO*PLANE)       // 262144
#define TOTAL (T_STEPS*FRAME)  // 33554432

// conv scratch (static __device__ array: allocation-free per harness rules)
__device__ float g_conv[TOTAL];

#define TILE_H 8
#define TILE_W 16
#define XS_H   (TILE_H + 2)    // 10
#define XS_WD  (TILE_W + 2)    // 18
#define XS_STRIDE 19           // odd stride -> spread banks
#define CO_PER_BLK 32

// ---- packed f32x2 helpers (sm_103a FFMA2 path; only reachable via PTX) ----
__device__ __forceinline__ uint64_t pk2(float lo, float hi) {
    uint64_t r;
    asm("mov.b64 %0, {%1, %2};" : "=l"(r) : "f"(lo), "f"(hi));
    return r;
}
__device__ __forceinline__ void upk2(uint64_t v, float& lo, float& hi) {
    asm("mov.b64 {%0, %1}, %2;" : "=f"(lo), "=f"(hi) : "l"(v));
}
__device__ __forceinline__ uint64_t fma2(uint64_t a, uint64_t b, uint64_t c) {
    uint64_t r;
    asm("fma.rn.f32x2 %0, %1, %2, %3;" : "=l"(r) : "l"(a), "l"(b), "l"(c));
    return r;
}

// ---------------------------------------------------------------------------
// Conv kernel: grid (32 spatial tiles, 2 co-groups, 128 t), 128 threads.
// Thread computes 8 c_out x 4 w at one h; c_out packed in PAIRS (f32x2 acc).
// x: scalar floats in smem (R3-proven path), packed (v,v) via MOV (ALU pipe).
// Weight pairs (c,c+1) contiguous in ws (co-fastest) -> warp-uniform LDS.64
// broadcasts. CO_PER_BLK=32 halves halo/prologue cost per FLOP vs R3.
// ---------------------------------------------------------------------------
__global__ __launch_bounds__(128, 5)
void conv_kernel(const float* __restrict__ x, const float* __restrict__ Wt,
                 const float* __restrict__ b) {
    __shared__ float xs[CIN * XS_H * XS_STRIDE];   // 3040 f = 12.2 KB
    __shared__ float ws[CIN * 9 * CO_PER_BLK];     // 4608 f = 18.4 KB

    const int tid  = threadIdx.x;
    const int t    = blockIdx.z;
    const int cog  = blockIdx.y;                   // co group (32 each)
    const int tile = blockIdx.x;                   // 0..31
    const int h0   = (tile >> 2) * TILE_H;
    const int w0   = (tile & 3) * TILE_W;
    const int co0  = cog * CO_PER_BLK;

    // Load weights: ws[(cin*9 + k)*32 + co_local]  (co fastest)
    #pragma unroll 4
    for (int i = tid; i < CIN * 9 * CO_PER_BLK; i += 128) {
        int col = i & 31;          // co local
        int k9  = i >> 5;          // cin*9 + kh*3 + kw
        ws[i] = Wt[(co0 + col) * (CIN * 9) + k9];
    }

    // Load x halo tile with zero padding (scalar floats)
    const float* xt = x + (size_t)t * (CIN * PLANE);
    #pragma unroll 4
    for (int i = tid; i < CIN * XS_H * XS_WD; i += 128) {
        int c   = i % XS_WD;
        int rc  = i / XS_WD;
        int r   = rc % XS_H;
        int cin = rc / XS_H;
        int y   = h0 - 1 + r;
        int xg  = w0 - 1 + c;
        float v = 0.0f;
        if ((unsigned)y < (unsigned)H && (unsigned)xg < (unsigned)W)
            v = xt[cin * PLANE + y * W + xg];
        xs[cin * (XS_H * XS_STRIDE) + r * XS_STRIDE + c] = v;
    }
    __syncthreads();

    const int co_sub = tid >> 5;            // 0..3  (uniform within warp)
    const int lane   = tid & 31;
    const int hl     = lane >> 2;           // 0..7
    const int wl     = (lane & 3) * 4;      // 0,4,8,12
    const int co_b   = co_sub * 8;          // local co base (8 c_out / thread)

    // acc[p][w] packs c_out pair (co_b+2p, co_b+2p+1) at output column w
    uint64_t acc[4][4];
    #pragma unroll
    for (int p = 0; p < 4; p++) {
        float b0 = b[co0 + co_b + 2 * p];
        float b1 = b[co0 + co_b + 2 * p + 1];
        uint64_t bp = pk2(b0, b1);
        #pragma unroll
        for (int w = 0; w < 4; w++) acc[p][w] = bp;
    }

    #pragma unroll
    for (int cin = 0; cin < CIN; cin++) {
        #pragma unroll
        for (int kh = 0; kh < 3; kh++) {
            const float* row =
                &xs[cin * (XS_H * XS_STRIDE) + (hl + kh) * XS_STRIDE + wl];
            uint64_t xx[6];
            #pragma unroll
            for (int j = 0; j < 6; j++) {
                float xv = row[j];
                xx[j] = pk2(xv, xv);
            }
            const float* wp = &ws[(cin * 9 + kh * 3) * CO_PER_BLK + co_b];
            #pragma unroll
            for (int p = 0; p < 4; p++) {
                // contiguous c-pairs -> aligned 8B warp-uniform broadcasts
                uint64_t wk0 = *(const uint64_t*)(wp + 2 * p);
                uint64_t wk1 = *(const uint64_t*)(wp + CO_PER_BLK + 2 * p);
                uint64_t wk2 = *(const uint64_t*)(wp + 2 * CO_PER_BLK + 2 * p);
                #pragma unroll
                for (int w = 0; w < 4; w++) {
                    acc[p][w] = fma2(xx[w],     wk0, acc[p][w]);
                    acc[p][w] = fma2(xx[w + 1], wk1, acc[p][w]);
                    acc[p][w] = fma2(xx[w + 2], wk2, acc[p][w]);
                }
            }
        }
    }

    // Unpack and store: one float4 per c_out (w-contiguous, 16B aligned)
    #pragma unroll
    for (int p = 0; p < 4; p++) {
        float lo[4], hi[4];
        #pragma unroll
        for (int w = 0; w < 4; w++) upk2(acc[p][w], lo[w], hi[w]);
        int co_e = co0 + co_b + 2 * p;
        size_t base = (size_t)t * FRAME + (h0 + hl) * W + (w0 + wl);
        *(float4*)&g_conv[base + (size_t)co_e * PLANE] =
            make_float4(lo[0], lo[1], lo[2], lo[3]);
        *(float4*)&g_conv[base + (size_t)(co_e + 1) * PLANE] =
            make_float4(hi[0], hi[1], hi[2], hi[3]);
    }
}

// ---------------------------------------------------------------------------
// Scan kernel: one thread per 4 adjacent (c_out,h,w) pixels; sequential LIF
// over T with float4 loads/stores (4x fewer L1tex wavefronts than scalar).
// ---------------------------------------------------------------------------
__device__ __forceinline__ void lif_step(float& s, float v, float& spike) {
    s += v;
    spike = (s >= 8.0f) ? 1.0f : 0.0f;       // fire
    s = (s >= 8.0f) ? 0.0f : s;              // reset-to-value 0
    s = (s > -1.0f) ? s : -1.0f;             // Threshold(-1,-1)
}

__global__ __launch_bounds__(128)
void scan_kernel(float* __restrict__ out) {
    const int idx = (blockIdx.x * 128 + threadIdx.x) * 4;   // < FRAME
    const float4* cp = (const float4*)(g_conv + idx);
    float4* op = (float4*)(out + idx);
    float4 s = make_float4(0.f, 0.f, 0.f, 0.f);
    #pragma unroll 8
    for (int t = 0; t < T_STEPS; t++) {
        float4 v = cp[(size_t)t * (FRAME / 4)];
        float4 r;
        lif_step(s.x, v.x, r.x);
        lif_step(s.y, v.y, r.y);
        lif_step(s.z, v.z, r.z);
        lif_step(s.w, v.w, r.w);
        op[(size_t)t * (FRAME / 4)] = r;
    }
}

extern "C" void kernel_launch(void* const* d_in, const int* in_sizes, int n_in,
                              void* d_out, int out_size) {
    // Identify inputs by unique element counts (robust to ordering)
    const float* x  = nullptr;
    const float* Wt = nullptr;
    const float* b  = nullptr;
    for (int i = 0; i < n_in; i++) {
        if (in_sizes[i] == T_STEPS * CIN * PLANE) x  = (const float*)d_in[i];
        else if (in_sizes[i] == CO * CIN * 9)     Wt = (const float*)d_in[i];
        else if (in_sizes[i] == CO)               b  = (const float*)d_in[i];
    }
    float* out = (float*)d_out;

    dim3 grid(32, 2, T_STEPS);      // 8192 blocks
    conv_kernel<<<grid, 128>>>(x, Wt, b);
    scan_kernel<<<FRAME / 4 / 128, 128>>>(out);   // 512 blocks x 128
}